// round 11
// baseline (speedup 1.0000x reference)
#include <cuda_runtime.h>
#include <cuda_bf16.h>
#include <cstdint>
#include <math.h>

typedef uint32_t u32;

#define HDIM 512
#define G4   2048
#define EDIM 256
#define N_SC 640
#define T_SC 128
#define N_CM 640
#define T_CM 64
#define N_ISP 128
#define N_IS_REAL 64
#define T_IS 32

#define KS_HH 32              // 512/16
#define KS_IH 16              // 256/16
#define NB_HH (256*KS_HH*32)  // uint2 elements
#define NB_IH (256*KS_IH*32)
#define ASTR  40              // smem A tile stride in bf16 (conflict-free)

#define STEP_SMEM (128*132*4) // z staging 67584 B (A tiles overlap at offset 0)

// ---------------- device globals ----------------
__device__ uint2 g_WhhH[3][NB_HH], g_WhhL[3][NB_HH];
__device__ uint2 g_WihH[3][NB_IH], g_WihL[3][NB_IH];

__device__ __nv_bfloat16 g_ehi_sc[(size_t)N_SC*T_SC*EDIM], g_elo_sc[(size_t)N_SC*T_SC*EDIM];
__device__ __nv_bfloat16 g_ehi_cm[(size_t)N_CM*T_CM*EDIM], g_elo_cm[(size_t)N_CM*T_CM*EDIM];
__device__ __nv_bfloat16 g_ehi_is[(size_t)N_ISP*T_IS*EDIM], g_elo_is[(size_t)N_ISP*T_IS*EDIM];

__device__ float g_xp_sc[(size_t)N_SC*T_SC*G4];
__device__ float g_xp_cm[(size_t)N_CM*T_CM*G4];
__device__ float g_xp_is[(size_t)N_ISP*T_IS*G4];

__device__ __nv_bfloat16 g_hhi_sc[2][N_SC*HDIM], g_hlo_sc[2][N_SC*HDIM];
__device__ __nv_bfloat16 g_hhi_cm[2][N_CM*HDIM], g_hlo_cm[2][N_CM*HDIM];
__device__ __nv_bfloat16 g_hhi_is[2][N_ISP*HDIM], g_hlo_is[2][N_ISP*HDIM];
__device__ float g_c_sc[N_SC*HDIM], g_c_cm[N_CM*HDIM], g_c_is[N_ISP*HDIM];
__device__ float g_hm[N_SC], g_cmm[N_SC];

// ---------------- helpers ----------------
__device__ __forceinline__ void mma_bf16(float* c, const u32* a, const u32* b) {
    asm volatile("mma.sync.aligned.m16n8k16.row.col.f32.bf16.bf16.f32 "
        "{%0,%1,%2,%3}, {%4,%5,%6,%7}, {%8,%9}, {%0,%1,%2,%3};"
        : "+f"(c[0]), "+f"(c[1]), "+f"(c[2]), "+f"(c[3])
        : "r"(a[0]), "r"(a[1]), "r"(a[2]), "r"(a[3]), "r"(b[0]), "r"(b[1]));
}
__device__ __forceinline__ u32 pk2(float a, float b) {
    __nv_bfloat162 v;
    v.x = __float2bfloat16(a); v.y = __float2bfloat16(b);
    return *(u32*)&v;
}
__device__ __forceinline__ float rsd(float a) {
    return a - __bfloat162float(__float2bfloat16(a));
}
__device__ __forceinline__ float sigf(float x) { return 1.f / (1.f + __expf(-x)); }
__device__ __forceinline__ float tanh_f(float x) { return 2.f / (1.f + __expf(-2.f * x)) - 1.f; }

// ---------------- prep kernels ----------------
__global__ void zero_state_k() {
    int i = blockIdx.x * blockDim.x + threadIdx.x;
    __nv_bfloat16 z = __float2bfloat16(0.f);
    if (i < N_SC * HDIM) {
        g_hhi_sc[0][i] = z; g_hlo_sc[0][i] = z; g_c_sc[i] = 0.f;
        g_hhi_cm[0][i] = z; g_hlo_cm[0][i] = z; g_c_cm[i] = 0.f;
    }
    if (i < N_ISP * HDIM) { g_hhi_is[0][i] = z; g_hlo_is[0][i] = z; g_c_is[i] = 0.f; }
}

__global__ void prep_w(const float* __restrict__ Whh, const float* __restrict__ Wih, int sel) {
    int idx = blockIdx.x * blockDim.x + threadIdx.x;
    if (idx < NB_HH) {
        int lane = idx & 31, rest = idx >> 5;
        int ks = rest % KS_HH, j8 = rest / KS_HH;
        int g = lane >> 2, tq = lane & 3;
        const float* Wr = Whh + (size_t)(j8 * 8 + g) * HDIM + ks * 16 + tq * 2;
        float w0 = Wr[0], w1 = Wr[1], w8 = Wr[8], w9 = Wr[9];
        g_WhhH[sel][idx] = make_uint2(pk2(w0, w1), pk2(w8, w9));
        g_WhhL[sel][idx] = make_uint2(pk2(rsd(w0), rsd(w1)), pk2(rsd(w8), rsd(w9)));
    } else {
        int id2 = idx - NB_HH;
        if (id2 < NB_IH) {
            int lane = id2 & 31, rest = id2 >> 5;
            int ks = rest % KS_IH, j8 = rest / KS_IH;
            int g = lane >> 2, tq = lane & 3;
            const float* Wr = Wih + (size_t)(j8 * 8 + g) * EDIM + ks * 16 + tq * 2;
            float w0 = Wr[0], w1 = Wr[1], w8 = Wr[8], w9 = Wr[9];
            g_WihH[sel][id2] = make_uint2(pk2(w0, w1), pk2(w8, w9));
            g_WihL[sel][id2] = make_uint2(pk2(rsd(w0), rsd(w1)), pk2(rsd(w8), rsd(w9)));
        }
    }
}

__global__ void prep_embed(const int* __restrict__ ids, const float* __restrict__ emb,
                           int sel, int Nreal, int Npad, int T) {
    __nv_bfloat16* hi = sel == 0 ? g_ehi_sc : sel == 1 ? g_ehi_cm : g_ehi_is;
    __nv_bfloat16* lo = sel == 0 ? g_elo_sc : sel == 1 ? g_elo_cm : g_elo_is;
    size_t idx = (size_t)blockIdx.x * blockDim.x + threadIdx.x;
    size_t total = (size_t)Npad * T * 64;
    if (idx >= total) return;
    int q = (int)(idx & 63);
    size_t r = idx >> 6;
    int n = (int)(r % Npad);
    int tt = (int)(r / Npad);
    float4 v = make_float4(0.f, 0.f, 0.f, 0.f);
    if (n < Nreal) {
        int tok = ids[(size_t)n * T + tt];
        v = ((const float4*)(emb + (size_t)tok * EDIM))[q];
    }
    __nv_bfloat16 h0 = __float2bfloat16(v.x), h1 = __float2bfloat16(v.y);
    __nv_bfloat16 h2 = __float2bfloat16(v.z), h3 = __float2bfloat16(v.w);
    size_t o = r * EDIM + (size_t)q * 4;
    __nv_bfloat162* ph = (__nv_bfloat162*)(hi + o);
    __nv_bfloat162* pl = (__nv_bfloat162*)(lo + o);
    ph[0] = __nv_bfloat162(h0, h1); ph[1] = __nv_bfloat162(h2, h3);
    pl[0] = __nv_bfloat162(__float2bfloat16(v.x - __bfloat162float(h0)),
                           __float2bfloat16(v.y - __bfloat162float(h1)));
    pl[1] = __nv_bfloat162(__float2bfloat16(v.z - __bfloat162float(h2)),
                           __float2bfloat16(v.w - __bfloat162float(h3)));
}

// ---------------- xproj GEMM: pipelined HMMA, M=64 x N=128 tile ----------------
__global__ void __launch_bounds__(256, 2)
xproj_mma(int sel, const float* __restrict__ bias) {
    const __nv_bfloat16* ehi = sel == 0 ? g_ehi_sc : sel == 1 ? g_ehi_cm : g_ehi_is;
    const __nv_bfloat16* elo = sel == 0 ? g_elo_sc : sel == 1 ? g_elo_cm : g_elo_is;
    const uint2* __restrict__ BHp = g_WihH[sel];
    const uint2* __restrict__ BLp = g_WihL[sel];
    float* xp = sel == 0 ? g_xp_sc : sel == 1 ? g_xp_cm : g_xp_is;

    __shared__ __nv_bfloat16 Ah[64 * ASTR], Al[64 * ASTR];

    const int tid = threadIdx.x, lane = tid & 31, warp = tid >> 5;
    const int wm = warp & 1, wn = warp >> 1;      // wm: 2x32 rows, wn: 4x32 cols
    const int g = lane >> 2, tq = lane & 3;
    const int m0 = blockIdx.x * 64;
    const int n0 = blockIdx.y * 128;

    const int ar = tid >> 2, aq = tid & 3;        // A copy role: row, 16B-quarter
    const u32 asts = (u32)(ar * ASTR + aq * 8);

    float acc[2][4][4];
#pragma unroll
    for (int i = 0; i < 2; i++)
#pragma unroll
        for (int j = 0; j < 4; j++)
#pragma unroll
            for (int q = 0; q < 4; q++) acc[i][j][q] = 0.f;

    {
        size_t off = (size_t)(m0 + ar) * EDIM + aq * 8;
        uint4 vh = *(const uint4*)(ehi + off);
        uint4 vl = *(const uint4*)(elo + off);
        *(uint4*)(Ah + asts) = vh;
        *(uint4*)(Al + asts) = vl;
    }
    __syncthreads();

#pragma unroll 1
    for (int ch = 0; ch < EDIM / 32; ch++) {
        uint4 nh, nl;
        bool has_next = (ch + 1) < EDIM / 32;
        if (has_next) {
            size_t off = (size_t)(m0 + ar) * EDIM + (ch + 1) * 32 + aq * 8;
            nh = *(const uint4*)(ehi + off);
            nl = *(const uint4*)(elo + off);
        }
        uint2 BH[2][4], BL[2][4];
#pragma unroll
        for (int kk = 0; kk < 2; kk++)
#pragma unroll
            for (int j = 0; j < 4; j++) {
                int j8 = (n0 >> 3) + wn * 4 + j;
                int bi = (j8 * KS_IH + ch * 2 + kk) * 32 + lane;
                BH[kk][j] = BHp[bi];
                BL[kk][j] = BLp[bi];
            }
#pragma unroll
        for (int kk = 0; kk < 2; kk++) {
            u32 AHf[2][4], ALf[2][4];
#pragma unroll
            for (int i = 0; i < 2; i++) {
                const __nv_bfloat16* p = Ah + (wm * 32 + i * 16 + g) * ASTR + kk * 16 + tq * 2;
                AHf[i][0] = *(const u32*)p;
                AHf[i][1] = *(const u32*)(p + 8 * ASTR);
                AHf[i][2] = *(const u32*)(p + 8);
                AHf[i][3] = *(const u32*)(p + 8 * ASTR + 8);
                const __nv_bfloat16* q2 = Al + (wm * 32 + i * 16 + g) * ASTR + kk * 16 + tq * 2;
                ALf[i][0] = *(const u32*)q2;
                ALf[i][1] = *(const u32*)(q2 + 8 * ASTR);
                ALf[i][2] = *(const u32*)(q2 + 8);
                ALf[i][3] = *(const u32*)(q2 + 8 * ASTR + 8);
            }
#pragma unroll
            for (int j = 0; j < 4; j++) {
                u32 bh[2] = {BH[kk][j].x, BH[kk][j].y};
                u32 bl[2] = {BL[kk][j].x, BL[kk][j].y};
#pragma unroll
                for (int i = 0; i < 2; i++) {
                    mma_bf16(acc[i][j], AHf[i], bh);
                    mma_bf16(acc[i][j], ALf[i], bh);
                    mma_bf16(acc[i][j], AHf[i], bl);
                }
            }
        }
        __syncthreads();
        if (has_next) {
            *(uint4*)(Ah + asts) = nh;
            *(uint4*)(Al + asts) = nl;
            __syncthreads();
        }
    }

#pragma unroll
    for (int i = 0; i < 2; i++)
#pragma unroll
        for (int j = 0; j < 4; j++) {
            int row = m0 + wm * 32 + i * 16 + g;
            int col = n0 + wn * 32 + j * 8 + tq * 2;
            *(float2*)&xp[(size_t)row * G4 + col] =
                make_float2(acc[i][j][0] + bias[col], acc[i][j][1] + bias[col + 1]);
            *(float2*)&xp[(size_t)(row + 8) * G4 + col] =
                make_float2(acc[i][j][2] + bias[col], acc[i][j][3] + bias[col + 1]);
        }
}

// ---------------- fused recurrent step: pipelined HMMA + gates ----------------
// tile: 128 rows x (4 gates x 32 hc).  grid: [0,80) sc ; [80,160) cm ; [160,176) is
__global__ void __launch_bounds__(256, 2)
step_mma(int t) {
    extern __shared__ char smem[];
    __nv_bfloat16* Ah = (__nv_bfloat16*)smem;
    __nv_bfloat16* Al = Ah + 128 * ASTR;
    float* zs = (float*)smem;   // reused after mainloop: [128][132]

    int bid = blockIdx.x;
    const __nv_bfloat16 *hhin, *hlin;
    __nv_bfloat16 *hhout, *hlout;
    const uint2 *__restrict__ BHp, *__restrict__ BLp;
    float* cst; const float* xp;
    int m0, hc0;

    if (bid < 80) {
        BHp = g_WhhH[0]; BLp = g_WhhL[0];
        hhin = g_hhi_sc[t & 1]; hlin = g_hlo_sc[t & 1];
        hhout = g_hhi_sc[(t + 1) & 1]; hlout = g_hlo_sc[(t + 1) & 1];
        cst = g_c_sc; xp = g_xp_sc + (size_t)t * N_SC * G4;
        m0 = (bid >> 4) * 128; hc0 = (bid & 15) * 32;
    } else if (bid < 160) {
        bid -= 80;
        BHp = g_WhhH[1]; BLp = g_WhhL[1];
        hhin = g_hhi_cm[t & 1]; hlin = g_hlo_cm[t & 1];
        hhout = g_hhi_cm[(t + 1) & 1]; hlout = g_hlo_cm[(t + 1) & 1];
        cst = g_c_cm; xp = g_xp_cm + (size_t)t * N_CM * G4;
        m0 = (bid >> 4) * 128; hc0 = (bid & 15) * 32;
    } else {
        bid -= 160;
        BHp = g_WhhH[2]; BLp = g_WhhL[2];
        hhin = g_hhi_is[t & 1]; hlin = g_hlo_is[t & 1];
        hhout = g_hhi_is[(t + 1) & 1]; hlout = g_hlo_is[(t + 1) & 1];
        cst = g_c_is; xp = g_xp_is + (size_t)t * N_ISP * G4;
        m0 = 0; hc0 = bid * 32;
    }

    const int tid = threadIdx.x, lane = tid & 31, warp = tid >> 5;
    const int wm = warp & 1, wn = warp >> 1;      // wm: 2x64 rows, wn = gate
    const int g = lane >> 2, tq = lane & 3;
    const int ar = tid >> 1, aq = tid & 1;        // A copy: row, 16-col half
    const u32 asts = (u32)(ar * ASTR + aq * 16);

    float acc[4][4][4];
#pragma unroll
    for (int i = 0; i < 4; i++)
#pragma unroll
        for (int j = 0; j < 4; j++)
#pragma unroll
            for (int q = 0; q < 4; q++) acc[i][j][q] = 0.f;

    {
        size_t off = (size_t)(m0 + ar) * HDIM + aq * 16;
        uint4 vh0 = *(const uint4*)(hhin + off);
        uint4 vh1 = *(const uint4*)(hhin + off + 8);
        uint4 vl0 = *(const uint4*)(hlin + off);
        uint4 vl1 = *(const uint4*)(hlin + off + 8);
        *(uint4*)(Ah + asts) = vh0; *(uint4*)(Ah + asts + 8) = vh1;
        *(uint4*)(Al + asts) = vl0; *(uint4*)(Al + asts + 8) = vl1;
    }
    __syncthreads();

#pragma unroll 1
    for (int ch = 0; ch < HDIM / 32; ch++) {
        uint4 nh0, nh1, nl0, nl1;
        bool has_next = (ch + 1) < HDIM / 32;
        if (has_next) {
            size_t off = (size_t)(m0 + ar) * HDIM + (ch + 1) * 32 + aq * 16;
            nh0 = *(const uint4*)(hhin + off);
            nh1 = *(const uint4*)(hhin + off + 8);
            nl0 = *(const uint4*)(hlin + off);
            nl1 = *(const uint4*)(hlin + off + 8);
        }
#pragma unroll
        for (int kk = 0; kk < 2; kk++) {
            uint2 BH[4], BL[4];
#pragma unroll
            for (int j = 0; j < 4; j++) {
                int j8 = wn * 64 + (hc0 >> 3) + j;        // gate = wn
                int bi = (j8 * KS_HH + ch * 2 + kk) * 32 + lane;
                BH[j] = BHp[bi];
                BL[j] = BLp[bi];
            }
            u32 AHf[4][4], ALf[4][4];
#pragma unroll
            for (int i = 0; i < 4; i++) {
                const __nv_bfloat16* p = Ah + (wm * 64 + i * 16 + g) * ASTR + kk * 16 + tq * 2;
                AHf[i][0] = *(const u32*)p;
                AHf[i][1] = *(const u32*)(p + 8 * ASTR);
                AHf[i][2] = *(const u32*)(p + 8);
                AHf[i][3] = *(const u32*)(p + 8 * ASTR + 8);
                const __nv_bfloat16* q2 = Al + (wm * 64 + i * 16 + g) * ASTR + kk * 16 + tq * 2;
                ALf[i][0] = *(const u32*)q2;
                ALf[i][1] = *(const u32*)(q2 + 8 * ASTR);
                ALf[i][2] = *(const u32*)(q2 + 8);
                ALf[i][3] = *(const u32*)(q2 + 8 * ASTR + 8);
            }
#pragma unroll
            for (int j = 0; j < 4; j++) {
                u32 bh[2] = {BH[j].x, BH[j].y};
                u32 bl[2] = {BL[j].x, BL[j].y};
#pragma unroll
                for (int i = 0; i < 4; i++) {
                    mma_bf16(acc[i][j], AHf[i], bh);
                    mma_bf16(acc[i][j], ALf[i], bh);
                    mma_bf16(acc[i][j], AHf[i], bl);
                }
            }
        }
        __syncthreads();
        if (has_next) {
            *(uint4*)(Ah + asts) = nh0; *(uint4*)(Ah + asts + 8) = nh1;
            *(uint4*)(Al + asts) = nl0; *(uint4*)(Al + asts + 8) = nl1;
            __syncthreads();
        }
    }

    // stage z into smem: col = gate*32 + hc_local  (gate = wn)
#pragma unroll
    for (int i = 0; i < 4; i++)
#pragma unroll
        for (int j = 0; j < 4; j++) {
            int row = wm * 64 + i * 16 + g;
            int colz = wn * 32 + j * 8 + tq * 2;
            *(float2*)&zs[row * 132 + colz] = make_float2(acc[i][j][0], acc[i][j][1]);
            *(float2*)&zs[(row + 8) * 132 + colz] = make_float2(acc[i][j][2], acc[i][j][3]);
        }
    __syncthreads();

    // pointwise: r = tid>>1, 16 contiguous hidden cols per thread
    {
        int r = tid >> 1;
        int hb = (tid & 1) * 16;
        int m = m0 + r;
#pragma unroll
        for (int half = 0; half < 4; half++) {
            int hc = hb + half * 4;
            int hcg = hc0 + hc;
            const float* zr = zs + r * 132 + hc;
            float4 zi = *(const float4*)(zr);
            float4 zf = *(const float4*)(zr + 32);
            float4 zg = *(const float4*)(zr + 64);
            float4 zo = *(const float4*)(zr + 96);
            const float* xr = xp + (size_t)m * G4 + hcg;
            float4 xi = *(const float4*)(xr);
            float4 xf = *(const float4*)(xr + 512);
            float4 xg = *(const float4*)(xr + 1024);
            float4 xo = *(const float4*)(xr + 1536);
            float vi[4] = {zi.x + xi.x, zi.y + xi.y, zi.z + xi.z, zi.w + xi.w};
            float vf[4] = {zf.x + xf.x, zf.y + xf.y, zf.z + xf.z, zf.w + xf.w};
            float vg[4] = {zg.x + xg.x, zg.y + xg.y, zg.z + xg.z, zg.w + xg.w};
            float vo[4] = {zo.x + xo.x, zo.y + xo.y, zo.z + xo.z, zo.w + xo.w};
            float* cp = cst + (size_t)m * HDIM + hcg;
            float4 cv = *(const float4*)cp;
            float cc[4] = {cv.x, cv.y, cv.z, cv.w};
            float hv[4];
#pragma unroll
            for (int q = 0; q < 4; q++) {
                float ig = sigf(vi[q]), fg = sigf(vf[q]);
                float gg = tanh_f(vg[q]), og = sigf(vo[q]);
                float cn = fg * cc[q] + ig * gg;
                cc[q] = cn;
                hv[q] = og * tanh_f(cn);
            }
            *(float4*)cp = make_float4(cc[0], cc[1], cc[2], cc[3]);
            __nv_bfloat16 h0 = __float2bfloat16(hv[0]), h1 = __float2bfloat16(hv[1]);
            __nv_bfloat16 h2 = __float2bfloat16(hv[2]), h3 = __float2bfloat16(hv[3]);
            __nv_bfloat162* ph = (__nv_bfloat162*)(hhout + (size_t)m * HDIM + hcg);
            ph[0] = __nv_bfloat162(h0, h1); ph[1] = __nv_bfloat162(h2, h3);
            __nv_bfloat162* pl = (__nv_bfloat162*)(hlout + (size_t)m * HDIM + hcg);
            pl[0] = __nv_bfloat162(__float2bfloat16(hv[0] - __bfloat162float(h0)),
                                   __float2bfloat16(hv[1] - __bfloat162float(h1)));
            pl[1] = __nv_bfloat162(__float2bfloat16(hv[2] - __bfloat162float(h2)),
                                   __float2bfloat16(hv[3] - __bfloat162float(h3)));
        }
    }
}

// ---------------- merge & final ----------------
__global__ void merge_kernel(const float* __restrict__ Wmh, const float* __restrict__ bmh,
                             const float* __restrict__ Wmc, const float* __restrict__ bmc)
{
    int wg = (blockIdx.x * blockDim.x + threadIdx.x) >> 5;
    int lane = threadIdx.x & 31;
    if (wg >= 2 * N_SC) return;
    int which = (wg >= N_SC);
    int n = which ? wg - N_SC : wg;
    const float* W = which ? Wmc : Wmh;
    float s = 0.f;
    for (int k = lane; k < HDIM; k += 32) {
        size_t i = (size_t)n * HDIM + k;
        float a, b;
        if (which) { a = g_c_sc[i]; b = g_c_cm[i]; }
        else {
            a = __bfloat162float(g_hhi_sc[0][i]) + __bfloat162float(g_hlo_sc[0][i]);
            b = __bfloat162float(g_hhi_cm[0][i]) + __bfloat162float(g_hlo_cm[0][i]);
        }
        s += a * W[k] + b * W[HDIM + k];
    }
#pragma unroll
    for (int off = 16; off > 0; off >>= 1) s += __shfl_down_sync(0xffffffffu, s, off);
    if (lane == 0) {
        if (which) g_cmm[n] = s + bmc[0];
        else       g_hm[n]  = s + bmh[0];
    }
}

__global__ void final_kernel(const float* __restrict__ Wfh, const float* __restrict__ bfh,
                             const float* __restrict__ Wfc, const float* __restrict__ bfc,
                             float* __restrict__ out)
{
    int gw = (blockIdx.x * blockDim.x + threadIdx.x) >> 5;
    int lane = threadIdx.x & 31;
    if (gw >= 2 * 64 * HDIM) return;
    int which = (gw >= 64 * HDIM);
    int rem = which ? gw - 64 * HDIM : gw;
    int b = rem >> 9, j = rem & 511;
    const float* W  = which ? Wfc : Wfh;
    const float* mv = which ? g_cmm : g_hm;
    const int K = 10 + HDIM;
    float s = 0.f;
    for (int k = lane; k < K; k += 32) {
        float x;
        if (k < 10) x = mv[b * 10 + k];
        else {
            size_t i = (size_t)b * HDIM + (k - 10);
            x = which ? g_c_is[i]
                      : __bfloat162float(g_hhi_is[0][i]) + __bfloat162float(g_hlo_is[0][i]);
        }
        s += W[(size_t)j * K + k] * x;
    }
#pragma unroll
    for (int off = 16; off > 0; off >>= 1) s += __shfl_down_sync(0xffffffffu, s, off);
    if (lane == 0) {
        float bias = which ? bfc[j] : bfh[j];
        out[(size_t)which * 64 * HDIM + (size_t)b * HDIM + j] = s + bias;
    }
}

// ---------------- launch ----------------
extern "C" void kernel_launch(void* const* d_in, const int* in_sizes, int n_in,
                              void* d_out, int out_size)
{
    (void)in_sizes; (void)n_in; (void)out_size;
    const int*   comments = (const int*)  d_in[0];
    const int*   cmids    = (const int*)  d_in[1];
    const int*   issue    = (const int*)  d_in[2];
    const float* emb_sc   = (const float*)d_in[3];
    const float* emb_cm   = (const float*)d_in[4];
    const float* emb_is   = (const float*)d_in[5];
    const float* Wih_sc   = (const float*)d_in[6];
    const float* Whh_sc   = (const float*)d_in[7];
    const float* b_sc     = (const float*)d_in[8];
    const float* Wih_cm   = (const float*)d_in[9];
    const float* Whh_cm   = (const float*)d_in[10];
    const float* b_cm     = (const float*)d_in[11];
    const float* Wih_is   = (const float*)d_in[12];
    const float* Whh_is   = (const float*)d_in[13];
    const float* b_is     = (const float*)d_in[14];
    const float* Wmh      = (const float*)d_in[15];
    const float* bmh      = (const float*)d_in[16];
    const float* Wmc      = (const float*)d_in[17];
    const float* bmc      = (const float*)d_in[18];
    const float* Wfh      = (const float*)d_in[19];
    const float* bfh      = (const float*)d_in[20];
    const float* Wfc      = (const float*)d_in[21];
    const float* bfc      = (const float*)d_in[22];

    cudaFuncSetAttribute(step_mma, cudaFuncAttributeMaxDynamicSharedMemorySize, STEP_SMEM);

    zero_state_k<<<(N_SC * HDIM + 255) / 256, 256>>>();
    prep_w<<<(NB_HH + NB_IH + 255) / 256, 256>>>(Whh_sc, Wih_sc, 0);
    prep_w<<<(NB_HH + NB_IH + 255) / 256, 256>>>(Whh_cm, Wih_cm, 1);
    prep_w<<<(NB_HH + NB_IH + 255) / 256, 256>>>(Whh_is, Wih_is, 2);
    prep_embed<<<(int)(((size_t)N_SC * T_SC * 64 + 255) / 256), 256>>>(comments, emb_sc, 0, N_SC, N_SC, T_SC);
    prep_embed<<<(int)(((size_t)N_CM * T_CM * 64 + 255) / 256), 256>>>(cmids, emb_cm, 1, N_CM, N_CM, T_CM);
    prep_embed<<<(int)(((size_t)N_ISP * T_IS * 64 + 255) / 256), 256>>>(issue, emb_is, 2, N_IS_REAL, N_ISP, T_IS);

    xproj_mma<<<dim3(N_SC * T_SC / 64, 16), 256>>>(0, b_sc);
    xproj_mma<<<dim3(N_CM * T_CM / 64, 16), 256>>>(1, b_cm);
    xproj_mma<<<dim3(N_ISP * T_IS / 64, 16), 256>>>(2, b_is);

    for (int t = 0; t < T_SC; t++) {
        int blocks = 80 + ((t < T_CM) ? 80 : 0) + ((t < T_IS) ? 16 : 0);
        step_mma<<<blocks, 256, STEP_SMEM>>>(t);
    }

    merge_kernel<<<(2 * N_SC * 32 + 255) / 256, 256>>>(Wmh, bmh, Wmc, bmc);
    final_kernel<<<(2 * 64 * HDIM * 32 + 255) / 256, 256>>>(Wfh, bfh, Wfc, bfc, (float*)d_out);
}